// round 9
// baseline (speedup 1.0000x reference)
#include <cuda_runtime.h>

// DigitCaps dynamic routing, GB300 sm_103a — R9: L2-resident u_hat cache.
// B=64, I=4096, Din=8, N=10, D=16, 3 routing iterations.
//
// R9 vs R8 (107.9 best; recompute-fused k_pass stuck at ~40us, issue 42%):
//  - routing is per-batch independent -> process 32-batch halves serially
//  - per half: u_hat fp32 = 84MB, fits L2. k_uhat computes u once (+ pass-0
//    sum); k_rpass<1,2> stream u from L2 (no recompute): ~18 instr/thread-il,
//    1 ffma2 agreement + 3-shfl tree + lag-2 pipelined softmax Z
//  - u loads __ldcg (no reuse), prefetch distance 2

#define B_ 64
#define I_ 4096
#define P_ 8
#define N_ 10
#define D_ 16
#define ND_ 160
#define HB 32                    // batches per half
#define POUT (HB * ND_)          // 5120 outputs per half
#define L2E 1.4426950408889634f

#define UTHREADS 320
#define UCH 296                  // k_uhat blocks (i-chunks of 14/13)
#define RICH 64                  // rpass i-chunks
#define RCH (I_ / RICH)          // 64 il per rpass block

// k_uhat smem (floats): x 32x64xfloat4 + W 2x1280
#define SMEM_U ((32 * 256 + 2 * 1280) * 4)   // 43,008 B

typedef unsigned long long ull;

__device__ ull   g_uhat[(size_t)I_ * HB * 80];   // f32x2: (i*32+ub)*80 + c2, 84MB
__device__ float g_partU[(size_t)UCH * POUT];    // 6.1MB
__device__ float g_partR[(size_t)RICH * POUT];   // 1.3MB
__device__ float g_blog[(size_t)I_ * HB * N_];   // 5.2MB (log2-domain logits)
__device__ float g_v[B_ * ND_];
__device__ float g_pad;

static __device__ __forceinline__ ull pack2(float a, float b) {
    ull r; asm("mov.b64 %0, {%1,%2};" : "=l"(r) : "f"(a), "f"(b)); return r;
}
static __device__ __forceinline__ float2 unpack2(ull v) {
    float2 r; asm("mov.b64 {%0,%1}, %2;" : "=f"(r.x), "=f"(r.y) : "l"(v)); return r;
}
static __device__ __forceinline__ ull ffma2(ull a, ull b, ull c) {
    ull d; asm("fma.rn.f32x2 %0, %1, %2, %3;" : "=l"(d) : "l"(a), "l"(b), "l"(c)); return d;
}
static __device__ __forceinline__ ull fadd2(ull a, ull b) {
    ull d; asm("add.rn.f32x2 %0, %1, %2;" : "=l"(d) : "l"(a), "l"(b)); return d;
}
static __device__ __forceinline__ float fast_ex2(float x) {
    float r; asm("ex2.approx.f32 %0, %1;" : "=f"(r) : "f"(x)); return r;
}
static __device__ __forceinline__ void cp16(unsigned dst, const void* src) {
    asm volatile("cp.async.cg.shared.global [%0], [%1], 16;" :: "r"(dst), "l"(src));
}
static __device__ __forceinline__ void cp_commit() {
    asm volatile("cp.async.commit_group;");
}
static __device__ __forceinline__ void cp_wait0() {
    asm volatile("cp.async.wait_group 0;" ::: "memory");
}

__global__ void k_pad() { g_pad = 0.0f; }

// ============================================================================
// k_uhat: compute u_hat for one 32-batch half, store fp32 (84MB, L2-resident),
// and accumulate the pass-0 (uniform c) partial sums.
// grid (296), 320 threads, 2 blocks/SM. lane = 16bb x 2dh, warp = n, BTILE 2.
// ============================================================================
__global__ __launch_bounds__(UTHREADS, 2) void k_uhat(const float* __restrict__ Xh,
                                                      const float* __restrict__ W) {
    extern __shared__ float smem[];
    float4* s_x4 = (float4*)smem;        // [lb<32][f4<64] swizzled
    float*  s_w  = smem + 32 * 256;      // [2][1280]

    const int tid = threadIdx.x;
    const int n   = tid >> 5;
    const int l   = tid & 31;
    const int bb  = l & 15;
    const int dh  = l >> 4;
    const int cb  = blockIdx.x;
    int i0, ni;
    if (cb < 248) { i0 = cb * 14; ni = 14; }
    else          { i0 = 3472 + (cb - 248) * 13; ni = 13; }
    const int b1 = bb;
    const int b2 = bb + 16;

    // stage x: 32 rows x ni*2 float4, swizzled
    {
        int nf = ni * 2;
        for (int idx = tid; idx < 32 * nf; idx += UTHREADS) {
            int lb = idx / nf;
            int f  = idx - lb * nf;
            float4 val = ((const float4*)(Xh + (size_t)lb * (I_ * P_) + i0 * P_))[f];
            s_x4[lb * 64 + (f ^ (lb & 7))] = val;
        }
    }
    // stage W(0)
    unsigned swb = (unsigned)__cvta_generic_to_shared(s_w);
    cp16(swb + tid * 16, W + (size_t)i0 * 1280 + tid * 4);
    cp_commit();
    cp_wait0();
    __syncthreads();

    ull sa[4], sb[4];
#pragma unroll
    for (int j = 0; j < 4; j++) { sa[j] = 0ULL; sb[j] = 0ULL; }

    const float4* sxa = s_x4 + bb * 64;
    const float4* sxb = s_x4 + (bb + 16) * 64;
    const int swz = bb & 7;

    for (int il = 0; il < ni; il++) {
        const int cur = il & 1;
        if (il + 1 < ni) {
            cp16(swb + (1 - cur) * 5120 + tid * 16,
                 W + (size_t)(i0 + il + 1) * 1280 + tid * 4);
            cp_commit();
        }

        float xa[8], xb[8];
        {
            int c0i = (il * 2) ^ swz;
            int c1i = c0i ^ 1;
            float4 a0 = sxa[c0i], a1 = sxa[c1i];
            float4 c0 = sxb[c0i], c1 = sxb[c1i];
            xa[0] = a0.x; xa[1] = a0.y; xa[2] = a0.z; xa[3] = a0.w;
            xa[4] = a1.x; xa[5] = a1.y; xa[6] = a1.z; xa[7] = a1.w;
            xb[0] = c0.x; xb[1] = c0.y; xb[2] = c0.z; xb[3] = c0.w;
            xb[4] = c1.x; xb[5] = c1.y; xb[6] = c1.z; xb[7] = c1.w;
        }

        ull t2a[4], t2b[4];
#pragma unroll
        for (int j = 0; j < 4; j++) { t2a[j] = 0ULL; t2b[j] = 0ULL; }
        {
            const float* wb = s_w + cur * 1280 + n * 128 + dh * 8;
#pragma unroll
            for (int p = 0; p < P_; p++) {
                ull xpa = pack2(xa[p], xa[p]);
                ull xpb = pack2(xb[p], xb[p]);
                ulonglong2 w0 = *(const ulonglong2*)(wb + p * 16);
                ulonglong2 w1 = *(const ulonglong2*)(wb + p * 16 + 4);
                t2a[0] = ffma2(xpa, w0.x, t2a[0]); t2a[1] = ffma2(xpa, w0.y, t2a[1]);
                t2a[2] = ffma2(xpa, w1.x, t2a[2]); t2a[3] = ffma2(xpa, w1.y, t2a[3]);
                t2b[0] = ffma2(xpb, w0.x, t2b[0]); t2b[1] = ffma2(xpb, w0.y, t2b[1]);
                t2b[2] = ffma2(xpb, w1.x, t2b[2]); t2b[3] = ffma2(xpb, w1.y, t2b[3]);
            }
        }
        // accumulate pass-0 sum
#pragma unroll
        for (int j = 0; j < 4; j++) {
            sa[j] = fadd2(sa[j], t2a[j]);
            sb[j] = fadd2(sb[j], t2b[j]);
        }
        // store u_hat: two 16B stores per batch fill one 32B sector
        {
            size_t r1 = ((size_t)(i0 + il) * HB + b1) * 80 + n * 8 + dh * 4;
            size_t r2 = ((size_t)(i0 + il) * HB + b2) * 80 + n * 8 + dh * 4;
            ulonglong2* q1 = (ulonglong2*)(g_uhat + r1);
            ulonglong2* q2 = (ulonglong2*)(g_uhat + r2);
            q1[0] = make_ulonglong2(t2a[0], t2a[1]);
            q1[1] = make_ulonglong2(t2a[2], t2a[3]);
            q2[0] = make_ulonglong2(t2b[0], t2b[1]);
            q2[1] = make_ulonglong2(t2b[2], t2b[3]);
        }
        cp_wait0();
        __syncthreads();
    }

    // per-chunk partials (c = 1/10 folded in)
    {
        float* p1 = g_partU + (size_t)cb * POUT + b1 * ND_ + n * D_ + dh * 8;
        float* p2 = g_partU + (size_t)cb * POUT + b2 * ND_ + n * D_ + dh * 8;
        float2 a0 = unpack2(sa[0]), a1 = unpack2(sa[1]);
        float2 a2 = unpack2(sa[2]), a3 = unpack2(sa[3]);
        float2 c0 = unpack2(sb[0]), c1 = unpack2(sb[1]);
        float2 c2 = unpack2(sb[2]), c3 = unpack2(sb[3]);
        *(float4*)(p1)     = make_float4(a0.x * .1f, a0.y * .1f, a1.x * .1f, a1.y * .1f);
        *(float4*)(p1 + 4) = make_float4(a2.x * .1f, a2.y * .1f, a3.x * .1f, a3.y * .1f);
        *(float4*)(p2)     = make_float4(c0.x * .1f, c0.y * .1f, c1.x * .1f, c1.y * .1f);
        *(float4*)(p2 + 4) = make_float4(c2.x * .1f, c2.y * .1f, c3.x * .1f, c3.y * .1f);
    }
}

// ============================================================================
// k_rpass<PASS>: one routing iteration streaming u_hat from L2.
// grid (64 ich, 8 ubg), 320 threads: thread = (ub4<4, c2<80); c2 = n*8+dq,
// thread owns f32x2 u[ub, i, n, 2d]. Lag-2 softmax pipeline, 1 barrier/il.
// ============================================================================
template <int PASS>
__global__ __launch_bounds__(320) void k_rpass(int half) {
    __shared__ float s_e[2][48];   // [buf][ub4*11 + n]
    __shared__ float s_z[2][4];

    const int t   = threadIdx.x;
    const int ub4 = t / 80;
    const int c2  = t % 80;
    const int n   = c2 >> 3;
    const int dq  = c2 & 7;
    const int ich = blockIdx.x;
    const int ub  = blockIdx.y * 4 + ub4;
    const int i0  = ich * RCH;

    // v (log2-scaled) for this thread's (ub, n, d-pair)
    ull v2;
    {
        const float2 vf = *(const float2*)(g_v + half * POUT + ub * ND_ + n * D_ + dq * 2);
        v2 = pack2(vf.x * L2E, vf.y * L2E);
    }
    const ull* up = g_uhat + ((size_t)i0 * HB + ub) * 80 + c2;
    float* bp = g_blog + ((size_t)i0 * HB + ub) * N_ + n;

    // prefetch u(0), u(1) (and pass-2 logits)
    ull uf0 = __ldcg(up), uf1 = __ldcg(up + 2560);
    float lf0 = 0.f, lf1 = 0.f;
    if (PASS == 2) { lf0 = __ldcg(bp); lf1 = __ldcg(bp + HB * N_); }

    ull u0 = 0ULL, u1 = 0ULL, sacc = 0ULL;
    float e0 = 0.f, e1 = 0.f;

    for (int il = 0; il < RCH; il++) {
        const int cur = il & 1;
        const ull u = uf0;
        const float lp = lf0;
        uf0 = uf1; lf0 = lf1;
        if (il + 2 < RCH) {
            uf1 = __ldcg(up + (size_t)(il + 2) * 2560);
            if (PASS == 2) lf1 = __ldcg(bp + (size_t)(il + 2) * (HB * N_));
        }

        // agreement: a[ub,n] = sum_d u*v (3-shfl tree over the 8 dq lanes)
        float2 af = unpack2(ffma2(u, v2, 0ULL));
        float a = af.x + af.y;
        a += __shfl_xor_sync(0xffffffffu, a, 1);
        a += __shfl_xor_sync(0xffffffffu, a, 2);
        a += __shfl_xor_sync(0xffffffffu, a, 4);
        float bn = (PASS == 2) ? a + lp : a;
        if (PASS == 1 && dq == 0) bp[(size_t)il * (HB * N_)] = bn;
        float e = fast_ex2(bn);
        if (dq == 0) s_e[cur][ub4 * 11 + n] = e;

        // produce Z(il-1) (4 threads)
        if (il > 0 && t < 4) {
            const float* se = &s_e[1 - cur][t * 11];
            s_z[1 - cur][t] = (((se[0] + se[1]) + (se[2] + se[3])) +
                               ((se[4] + se[5]) + (se[6] + se[7]))) + (se[8] + se[9]);
        }
        // consume il-2
        if (il >= 2) {
            float Z = s_z[cur][ub4];
            float c = __fdividef(e0, Z);
            sacc = ffma2(pack2(c, c), u0, sacc);
        }
        __syncthreads();
        u0 = u1; u1 = u; e0 = e1; e1 = e;
    }

    // drain: produce Z(RCH-1), consume RCH-2, barrier, consume RCH-1
    if (t < 4) {
        const float* se = &s_e[(RCH - 1) & 1][t * 11];
        s_z[(RCH - 1) & 1][t] = (((se[0] + se[1]) + (se[2] + se[3])) +
                                 ((se[4] + se[5]) + (se[6] + se[7]))) + (se[8] + se[9]);
    }
    {
        float Z = s_z[(RCH - 2) & 1][ub4];
        float c = __fdividef(e0, Z);
        sacc = ffma2(pack2(c, c), u0, sacc);
    }
    __syncthreads();
    {
        float Z = s_z[(RCH - 1) & 1][ub4];
        float c = __fdividef(e1, Z);
        sacc = ffma2(pack2(c, c), u1, sacc);
    }

    // partial (coalesced STG.64)
    ((ull*)g_partR)[(size_t)ich * 2560 + ub * 80 + c2] = sacc;
}

// ============================================================================
// Reductions + squash (fixed order, deterministic)
// ============================================================================
template <bool FINAL>
__global__ __launch_bounds__(512) void k_finishU(int half, float* __restrict__ dout) {
    __shared__ float red[16][33];
    int tid = threadIdx.x;
    int s = tid >> 5;
    int ol = tid & 31;
    int o = blockIdx.x * 32 + ol;          // grid 160 -> 5120 outs

    int start = (s < 8) ? s * 19 : 152 + (s - 8) * 18;
    int cnt = (s < 8) ? 19 : 18;
    const float* p = g_partU + (size_t)start * POUT + o;
    float a0 = 0.f, a1 = 0.f, a2 = 0.f, a3 = 0.f;
    int k = 0;
    for (; k + 4 <= cnt; k += 4) {
        a0 += p[(size_t)(k + 0) * POUT];
        a1 += p[(size_t)(k + 1) * POUT];
        a2 += p[(size_t)(k + 2) * POUT];
        a3 += p[(size_t)(k + 3) * POUT];
    }
    for (; k < cnt; k++) a0 += p[(size_t)k * POUT];
    red[s][ol] = (a0 + a1) + (a2 + a3);
    __syncthreads();

    if (s == 0) {
        float t0 = (red[0][ol] + red[1][ol]) + (red[2][ol] + red[3][ol]);
        float t1 = (red[4][ol] + red[5][ol]) + (red[6][ol] + red[7][ol]);
        float t2 = (red[8][ol] + red[9][ol]) + (red[10][ol] + red[11][ol]);
        float t3 = (red[12][ol] + red[13][ol]) + (red[14][ol] + red[15][ol]);
        float sv = (t0 + t1) + (t2 + t3);
        float sq = sv * sv;
        float scale = sq / ((1.f + sq) * sqrtf(sq + 1e-7f));
        float v = scale * sv;
        float* dst = FINAL ? (dout + half * POUT) : (g_v + half * POUT);
        dst[o] = v;
    }
}

template <bool FINAL>
__global__ __launch_bounds__(256) void k_finishR(int half, float* __restrict__ dout) {
    __shared__ float red[8][33];
    int tid = threadIdx.x;
    int s = tid >> 5;                       // 8 slices x 8 deep = 64
    int ol = tid & 31;
    int o = blockIdx.x * 32 + ol;           // grid 160 -> 5120 outs

    const float* p = g_partR + (size_t)(s * 8) * POUT + o;
    float a0 = 0.f, a1 = 0.f, a2 = 0.f, a3 = 0.f;
#pragma unroll
    for (int k = 0; k < 8; k += 4) {
        a0 += p[(size_t)(k + 0) * POUT];
        a1 += p[(size_t)(k + 1) * POUT];
        a2 += p[(size_t)(k + 2) * POUT];
        a3 += p[(size_t)(k + 3) * POUT];
    }
    red[s][ol] = (a0 + a1) + (a2 + a3);
    __syncthreads();

    if (s == 0) {
        float sv = ((red[0][ol] + red[1][ol]) + (red[2][ol] + red[3][ol])) +
                   ((red[4][ol] + red[5][ol]) + (red[6][ol] + red[7][ol]));
        float sq = sv * sv;
        float scale = sq / ((1.f + sq) * sqrtf(sq + 1e-7f));
        float v = scale * sv;
        float* dst = FINAL ? (dout + half * POUT) : (g_v + half * POUT);
        dst[o] = v;
    }
}

extern "C" void kernel_launch(void* const* d_in, const int* in_sizes, int n_in,
                              void* d_out, int out_size) {
    const float* X = (const float*)d_in[0];
    const float* W = (const float*)d_in[1];
    if (n_in >= 2 && in_sizes[0] != B_ * I_ * P_) {
        const float* tmp = X; X = W; W = tmp;
    }

    cudaFuncSetAttribute(k_uhat, cudaFuncAttributeMaxDynamicSharedMemorySize, SMEM_U);

    dim3 rg(RICH, 8);
    k_pad<<<1, 1>>>();
    for (int h = 0; h < 2; h++) {
        k_uhat<<<UCH, UTHREADS, SMEM_U>>>(X + (size_t)h * HB * (I_ * P_), W);
        k_finishU<false><<<160, 512>>>(h, nullptr);
        k_rpass<1><<<rg, 320>>>(h);
        k_finishR<false><<<160, 256>>>(h, nullptr);
        k_rpass<2><<<rg, 320>>>(h);
        k_finishR<true><<<160, 256>>>(h, (float*)d_out);
    }
}

// round 11
// speedup vs baseline: 2.0131x; 2.0131x over previous
#include <cuda_runtime.h>

// DigitCaps dynamic routing, GB300 sm_103a — R11 (= R10 resubmit; infra fail).
// B=64, I=4096, Din=8, N=10, D=16, 3 routing iterations.
//
// R10/R11 vs R9 (231us DRAM-bound FAIL -> revert to recompute; R6 best 107.9):
//  - lane = 8bb x 4dq (d-quarter), BTILE=4 batches/thread:
//    W 16->8 wf/warp-il, x ->8 wf (batch-k instr: 8 distinct rows x 4 bcast)
//  - batch slot k owned by lane k=dq; cross-lane Z/logit via 3 shfl + SEL
//  - lean PASS0 (no softmax plumbing), PASS2 skips logit store
//  - everything else: proven R6 fabric (swizzled s_x, cp.async W, ex2, log2
//    domain logits, per-chunk partials + k_finish)

#define B_ 64
#define I_ 4096
#define P_ 8
#define N_ 10
#define D_ 16
#define ND_ 160
#define THREADS 320
#define OUT_ (B_ * ND_)
#define L2E 1.4426950408889634f

// dynamic smem (bytes): s_x 32KB + s_w 10KB + s_e 2.8KB
#define SX_F4 2048               // 32 rows x 64 float4 (swizzled)
#define SW_F (2 * 1280)
#define SE_F (2 * 352)
#define SMEM_BYTES (SX_F4 * 16 + SW_F * 4 + SE_F * 4)   // 45,824 B

__device__ float g_part[(size_t)148 * OUT_];
__device__ float g_blog[(size_t)I_ * 640];   // log2-domain logits [i][n*64+bh*32+l]
__device__ float g_v[OUT_];
__device__ float g_pad;

typedef unsigned long long ull;

static __device__ __forceinline__ ull pack2(float a, float b) {
    ull r; asm("mov.b64 %0, {%1,%2};" : "=l"(r) : "f"(a), "f"(b)); return r;
}
static __device__ __forceinline__ float2 unpack2(ull v) {
    float2 r; asm("mov.b64 {%0,%1}, %2;" : "=f"(r.x), "=f"(r.y) : "l"(v)); return r;
}
static __device__ __forceinline__ ull ffma2(ull a, ull b, ull c) {
    ull d; asm("fma.rn.f32x2 %0, %1, %2, %3;" : "=l"(d) : "l"(a), "l"(b), "l"(c)); return d;
}
static __device__ __forceinline__ ull fadd2(ull a, ull b) {
    ull d; asm("add.rn.f32x2 %0, %1, %2;" : "=l"(d) : "l"(a), "l"(b)); return d;
}
static __device__ __forceinline__ float fast_ex2(float x) {
    float r; asm("ex2.approx.f32 %0, %1;" : "=f"(r) : "f"(x)); return r;
}
static __device__ __forceinline__ void cp16(unsigned dst, const void* src) {
    asm volatile("cp.async.cg.shared.global [%0], [%1], 16;" :: "r"(dst), "l"(src));
}
static __device__ __forceinline__ void cp_commit() {
    asm volatile("cp.async.commit_group;");
}
static __device__ __forceinline__ void cp_wait0() {
    asm volatile("cp.async.wait_group 0;" ::: "memory");
}
// {a0,a1,a2,a3}[m] via predication (m = 0..3), no dynamic local indexing
static __device__ __forceinline__ float sel4(float a0, float a1, float a2, float a3, int m) {
    float lo = (m & 1) ? a1 : a0;
    float hi = (m & 1) ? a3 : a2;
    return (m & 2) ? hi : lo;
}

__global__ void k_pad() { g_pad = 0.0f; }

template <int PASS>
__global__ __launch_bounds__(THREADS, 2) void k_pass(const float* __restrict__ X,
                                                     const float* __restrict__ W) {
    extern __shared__ float smem[];
    float4* s_x4 = (float4*)smem;            // [lb<32][f4<64] swizzled
    float*  s_w  = smem + SX_F4 * 4;         // [2][1280]
    float*  s_e  = s_w + SW_F;               // [2][32*11]

    const int tid = threadIdx.x;
    const int n   = tid >> 5;                // warp = n
    const int l   = tid & 31;
    const int bb  = l & 7;
    const int dq  = l >> 3;                  // d-quarter 0..3
    const int cb  = blockIdx.x;
    const int bh  = blockIdx.y;
    int i0, ni;
    if (cb < 100) { i0 = cb * 28; ni = 28; }
    else          { i0 = 2800 + (cb - 100) * 27; ni = 27; }

    // ---- stage x: 32 local batches x ni*2 float4, swizzled (proven)
    {
        int nf = ni * 2;
        for (int idx = tid; idx < 32 * nf; idx += THREADS) {
            int lb = idx / nf;
            int f  = idx - lb * nf;
            float4 val = ((const float4*)(X + (size_t)(bh * 32 + lb) * (I_ * P_) + i0 * P_))[f];
            s_x4[lb * 64 + (f ^ (lb & 7))] = val;
        }
    }
    // ---- stage W(0) via cp.async (320 thr x 4 floats = 1280)
    unsigned swb = (unsigned)__cvta_generic_to_shared(s_w);
    cp16(swb + tid * 16, W + (size_t)i0 * 1280 + tid * 4);
    cp_commit();

    // ---- v (log2-scaled) for the 4 batches, this (n, dq)
    ull v2[4][2];
    if (PASS > 0) {
#pragma unroll
        for (int k = 0; k < 4; k++) {
            float4 f = *(const float4*)(g_v + (bh * 32 + k * 8 + bb) * ND_ + n * D_ + dq * 4);
            v2[k][0] = pack2(f.x * L2E, f.y * L2E);
            v2[k][1] = pack2(f.z * L2E, f.w * L2E);
        }
    }
    cp_wait0();
    __syncthreads();

    ull t2[4][2], sacc[4][2];
#pragma unroll
    for (int k = 0; k < 4; k++) { sacc[k][0] = 0ULL; sacc[k][1] = 0ULL; }

    float* gbp = g_blog + (size_t)i0 * 640 + n * 64 + bh * 32 + l;   // own batch = l

    for (int il = 0; il < ni; il++) {
        const int cur = il & 1;

        // stage W(il+1) into 1-cur (its last reader finished before prior barrier)
        if (il + 1 < ni) {
            cp16(swb + (1 - cur) * 5120 + tid * 16,
                 W + (size_t)(i0 + il + 1) * 1280 + tid * 4);
            cp_commit();
        }
        // (PASS2) own prior logit
        float gown = 0.f;
        if (PASS == 2) { gown = *gbp; }

        // ---- consume il-1 (t2 still holds t(il-1); e(il-1) in s_e[1-cur])
        if (PASS > 0 && il > 0) {
            const float* se = s_e + (1 - cur) * 352;
            const float* zr = se + l * 11;
            float Zo = (((zr[0] + zr[1]) + (zr[2] + zr[3])) +
                        ((zr[4] + zr[5]) + (zr[6] + zr[7]))) + (zr[8] + zr[9]);
            float z8  = __shfl_xor_sync(0xffffffffu, Zo, 8);
            float z16 = __shfl_xor_sync(0xffffffffu, Zo, 16);
            float z24 = __shfl_xor_sync(0xffffffffu, Zo, 24);
#pragma unroll
            for (int k = 0; k < 4; k++) {
                float Zk = sel4(Zo, z8, z16, z24, k ^ dq);
                float ek = se[(k * 8 + bb) * 11 + n];
                float c = __fdividef(ek, Zk);
                ull cp = pack2(c, c);
                sacc[k][0] = ffma2(cp, t2[k][0], sacc[k][0]);
                sacc[k][1] = ffma2(cp, t2[k][1], sacc[k][1]);
            }
        }

        // ---- x(il) for 4 batches (per-instr: 8 distinct rows x 4 bcast = 1 wf)
        ull xp[4][8];
        {
            int c0 = (il * 2) ^ bb;
            int c1 = c0 ^ 1;
#pragma unroll
            for (int k = 0; k < 4; k++) {
                const float4* row = s_x4 + (k * 8 + bb) * 64;
                float4 a = row[c0], b = row[c1];
                xp[k][0] = pack2(a.x, a.x); xp[k][1] = pack2(a.y, a.y);
                xp[k][2] = pack2(a.z, a.z); xp[k][3] = pack2(a.w, a.w);
                xp[k][4] = pack2(b.x, b.x); xp[k][5] = pack2(b.y, b.y);
                xp[k][6] = pack2(b.z, b.z); xp[k][7] = pack2(b.w, b.w);
            }
        }

        // ---- t(il) = u[b_k, i, n, dq*4..+3]
#pragma unroll
        for (int k = 0; k < 4; k++) { t2[k][0] = 0ULL; t2[k][1] = 0ULL; }
        {
            const float* wb = s_w + cur * 1280 + n * 128 + dq * 4;
#pragma unroll
            for (int p = 0; p < P_; p++) {
                ulonglong2 w = *(const ulonglong2*)(wb + p * 16);   // 4 floats, 64B/warp
#pragma unroll
                for (int k = 0; k < 4; k++) {
                    t2[k][0] = ffma2(xp[k][p], w.x, t2[k][0]);
                    t2[k][1] = ffma2(xp[k][p], w.y, t2[k][1]);
                }
            }
        }

        if (PASS == 0) {
#pragma unroll
            for (int k = 0; k < 4; k++) {
                sacc[k][0] = fadd2(sacc[k][0], t2[k][0]);
                sacc[k][1] = fadd2(sacc[k][1], t2[k][1]);
            }
        } else {
            // ---- agreement: pa[k] = sum_d u*v (in-thread + dq butterfly)
            float pa[4];
#pragma unroll
            for (int k = 0; k < 4; k++) {
                float2 f = unpack2(ffma2(t2[k][0], v2[k][0],
                                         ffma2(t2[k][1], v2[k][1], 0ULL)));
                pa[k] = f.x + f.y;
            }
#pragma unroll
            for (int k = 0; k < 4; k++) pa[k] += __shfl_xor_sync(0xffffffffu, pa[k], 8);
#pragma unroll
            for (int k = 0; k < 4; k++) pa[k] += __shfl_xor_sync(0xffffffffu, pa[k], 16);

            float bn[4];
            if (PASS == 2) {
                float g8  = __shfl_xor_sync(0xffffffffu, gown, 8);
                float g16 = __shfl_xor_sync(0xffffffffu, gown, 16);
                float g24 = __shfl_xor_sync(0xffffffffu, gown, 24);
#pragma unroll
                for (int k = 0; k < 4; k++)
                    bn[k] = pa[k] + sel4(gown, g8, g16, g24, k ^ dq);
            } else {
#pragma unroll
                for (int k = 0; k < 4; k++) bn[k] = pa[k];
            }

            float bn_own = sel4(bn[0], bn[1], bn[2], bn[3], dq);
            if (PASS == 1) *gbp = bn_own;        // PASS2 is last: no store needed
            float e_own = fast_ex2(bn_own);
            s_e[cur * 352 + l * 11 + n] = e_own;
            gbp += 640;
        }

        cp_wait0();
        __syncthreads();
    }

    // ---- epilogue: consume last il (PASS>0)
    if (PASS > 0) {
        const float* se = s_e + ((ni - 1) & 1) * 352;
        const float* zr = se + l * 11;
        float Zo = (((zr[0] + zr[1]) + (zr[2] + zr[3])) +
                    ((zr[4] + zr[5]) + (zr[6] + zr[7]))) + (zr[8] + zr[9]);
        float z8  = __shfl_xor_sync(0xffffffffu, Zo, 8);
        float z16 = __shfl_xor_sync(0xffffffffu, Zo, 16);
        float z24 = __shfl_xor_sync(0xffffffffu, Zo, 24);
#pragma unroll
        for (int k = 0; k < 4; k++) {
            float Zk = sel4(Zo, z8, z16, z24, k ^ dq);
            float ek = se[(k * 8 + bb) * 11 + n];
            float c = __fdividef(ek, Zk);
            ull cp = pack2(c, c);
            sacc[k][0] = ffma2(cp, t2[k][0], sacc[k][0]);
            sacc[k][1] = ffma2(cp, t2[k][1], sacc[k][1]);
        }
    }

    // ---- per-chunk partials (deterministic; layout = output layout)
#pragma unroll
    for (int k = 0; k < 4; k++) {
        float2 f0 = unpack2(sacc[k][0]);
        float2 f1 = unpack2(sacc[k][1]);
        float kk = (PASS == 0) ? 0.1f : 1.0f;
        *(float4*)(g_part + (size_t)cb * OUT_ +
                   (bh * 32 + k * 8 + bb) * ND_ + n * D_ + dq * 4) =
            make_float4(f0.x * kk, f0.y * kk, f1.x * kk, f1.y * kk);
    }
}

// 148-way reduction + squash. Grid 320 x 512: 16 slices (4x10 + 12x9 = 148).
template <bool FINAL>
__global__ __launch_bounds__(512) void k_finish(float* __restrict__ dout) {
    __shared__ float red[16][33];
    int tid = threadIdx.x;
    int s = tid >> 5;
    int ol = tid & 31;
    int o = blockIdx.x * 32 + ol;

    int start = (s < 4) ? s * 10 : 40 + (s - 4) * 9;
    int cnt = (s < 4) ? 10 : 9;
    const float* p = g_part + (size_t)start * OUT_ + o;
    float a0 = 0.f, a1 = 0.f, a2 = 0.f, a3 = 0.f;
    int k = 0;
    for (; k + 4 <= cnt; k += 4) {
        a0 += p[(size_t)(k + 0) * OUT_];
        a1 += p[(size_t)(k + 1) * OUT_];
        a2 += p[(size_t)(k + 2) * OUT_];
        a3 += p[(size_t)(k + 3) * OUT_];
    }
    for (; k < cnt; k++) a0 += p[(size_t)k * OUT_];
    red[s][ol] = (a0 + a1) + (a2 + a3);
    __syncthreads();

    if (s == 0) {
        float t0 = (red[0][ol] + red[1][ol]) + (red[2][ol] + red[3][ol]);
        float t1 = (red[4][ol] + red[5][ol]) + (red[6][ol] + red[7][ol]);
        float t2 = (red[8][ol] + red[9][ol]) + (red[10][ol] + red[11][ol]);
        float t3 = (red[12][ol] + red[13][ol]) + (red[14][ol] + red[15][ol]);
        float sv = (t0 + t1) + (t2 + t3);
        float sq = sv * sv;
        float scale = sq / ((1.f + sq) * sqrtf(sq + 1e-7f));
        float v = scale * sv;
        if (FINAL) dout[o] = v;
        else       g_v[o] = v;
    }
}

extern "C" void kernel_launch(void* const* d_in, const int* in_sizes, int n_in,
                              void* d_out, int out_size) {
    const float* X = (const float*)d_in[0];
    const float* W = (const float*)d_in[1];
    if (n_in >= 2 && in_sizes[0] != B_ * I_ * P_) {
        const float* tmp = X; X = W; W = tmp;
    }

    dim3 gp(148, 2);
    k_pad<<<1, 1>>>();
    k_pass<0><<<gp, THREADS, SMEM_BYTES>>>(X, W);
    k_finish<false><<<320, 512>>>(nullptr);
    k_pass<1><<<gp, THREADS, SMEM_BYTES>>>(X, W);
    k_finish<false><<<320, 512>>>(nullptr);
    k_pass<2><<<gp, THREADS, SMEM_BYTES>>>(X, W);
    k_finish<true><<<320, 512>>>((float*)d_out);
}

// round 12
// speedup vs baseline: 2.0921x; 1.0393x over previous
#include <cuda_runtime.h>

// DigitCaps dynamic routing, GB300 sm_103a — R12.
// B=64, I=4096, Din=8, N=10, D=16, 3 routing iterations.
//
// R12 = R6 k_pass verbatim (best measured: 39.2us/pass, 107.9 total) with the
// reduction path replaced:
//  - pass epilogue: 4x atomicAdd(float4*) into g_s (REDG.128, spread addrs)
//  - k_finish (3 x ~6us) -> k_squash (10240-thr elementwise, ~2us) which also
//    re-zeroes g_s for the next pass
//  - k_pad zeroes g_s initially (and keeps ncu -s 5 on k_pass<2>)
// R10/R11 lane-relayouts falsified (issue/latency floor, not wavefronts).

#define B_ 64
#define I_ 4096
#define P_ 8
#define N_ 10
#define D_ 16
#define ND_ 160
#define THREADS 320              // 32 b x 10 n, lane = 16bb x 2dh, BTILE=2
#define OUT_ (B_ * ND_)          // 10240
#define L2E 1.4426950408889634f

#define SX_STRIDE 236
#define SX_SZ (32 * SX_STRIDE)   // 7552 floats
#define SW_SZ (2 * 1280)         // 2560
#define SE_SZ (2 * 352)          // 704
#define SMEM_BYTES ((SX_SZ + SW_SZ + SE_SZ) * 4)   // 43,264 B (< 48K default)

__device__ float g_s[OUT_];                     // atomic accumulator
__device__ float g_blog[(size_t)I_ * 640];      // log2-domain logits [i][n*64+bh*32+l]
__device__ float g_v[OUT_];                     // squashed v

typedef unsigned long long ull;

static __device__ __forceinline__ ull pack2(float a, float b) {
    ull r; asm("mov.b64 %0, {%1,%2};" : "=l"(r) : "f"(a), "f"(b)); return r;
}
static __device__ __forceinline__ float2 unpack2(ull v) {
    float2 r; asm("mov.b64 {%0,%1}, %2;" : "=f"(r.x), "=f"(r.y) : "l"(v)); return r;
}
static __device__ __forceinline__ ull ffma2(ull a, ull b, ull c) {
    ull d; asm("fma.rn.f32x2 %0, %1, %2, %3;" : "=l"(d) : "l"(a), "l"(b), "l"(c)); return d;
}
static __device__ __forceinline__ ull fadd2(ull a, ull b) {
    ull d; asm("add.rn.f32x2 %0, %1, %2;" : "=l"(d) : "l"(a), "l"(b)); return d;
}
static __device__ __forceinline__ float fast_ex2(float x) {
    float r; asm("ex2.approx.f32 %0, %1;" : "=f"(r) : "f"(x)); return r;
}

// launch #0: zero g_s (also pins ncu -s 5 -c 1 onto k_pass<2>)
__global__ __launch_bounds__(256) void k_pad() {
    int idx = blockIdx.x * 256 + threadIdx.x;
    if (idx < OUT_) g_s[idx] = 0.0f;
}

template <int PASS>
__global__ __launch_bounds__(THREADS, 2) void k_pass(const float* __restrict__ X,
                                                     const float* __restrict__ W) {
    extern __shared__ float smem[];
    float* s_x = smem;                 // [lb][r] stride SX_STRIDE
    float* s_w = smem + SX_SZ;         // 2 x 1280
    float* s_e = s_w + SW_SZ;          // 2 x (32*11)

    const int tid = threadIdx.x;
    const int n   = tid >> 5;          // warp id = n
    const int l   = tid & 31;          // lane
    const int bb  = l & 15;
    const int dh  = l >> 4;            // d-half
    const int cb  = blockIdx.x;        // i-chunk
    const int bh  = blockIdx.y;        // batch half
    int i0, ni;
    if (cb < 100) { i0 = cb * 28; ni = 28; }
    else          { i0 = 2800 + (cb - 100) * 27; ni = 27; }
    const int b1 = bh * 32 + bb;
    const int b2 = b1 + 16;

    // ---- stage x: rows = 32 local batches, ni*8 floats each
    {
        int nr = ni * 8;
        for (int idx = tid; idx < 32 * nr; idx += THREADS) {
            int lb = idx / nr;
            int r  = idx - lb * nr;
            s_x[lb * SX_STRIDE + r] = X[(size_t)(bh * 32 + lb) * (I_ * P_) + i0 * P_ + r];
        }
    }
    // ---- stage W(0)
    *(float4*)(s_w + tid * 4) = *(const float4*)(W + (size_t)i0 * 1280 + tid * 4);

    // ---- v (log2-scaled) for both batches, this thread's d-half
    ull v2a[4], v2b[4];
    if (PASS > 0) {
        const float4* va = (const float4*)(g_v + b1 * ND_ + n * D_ + dh * 8);
        const float4* vb = (const float4*)(g_v + b2 * ND_ + n * D_ + dh * 8);
        float4 a0 = va[0], a1 = va[1], c0 = vb[0], c1 = vb[1];
        v2a[0] = pack2(a0.x * L2E, a0.y * L2E); v2a[1] = pack2(a0.z * L2E, a0.w * L2E);
        v2a[2] = pack2(a1.x * L2E, a1.y * L2E); v2a[3] = pack2(a1.z * L2E, a1.w * L2E);
        v2b[0] = pack2(c0.x * L2E, c0.y * L2E); v2b[1] = pack2(c0.z * L2E, c0.w * L2E);
        v2b[2] = pack2(c1.x * L2E, c1.y * L2E); v2b[3] = pack2(c1.z * L2E, c1.w * L2E);
    }
    __syncthreads();

    ull t2a[4], t2b[4], sa[4], sb[4];
#pragma unroll
    for (int j = 0; j < 4; j++) { sa[j] = 0ULL; sb[j] = 0ULL; }
    float e1p = 0.f, e2p = 0.f;

    const float* wsrc = W + (size_t)(i0 + 1) * 1280 + tid * 4;
    float* gbp = g_blog + (size_t)i0 * 640 + n * 64 + bh * 32 + l;
    const float4* sxa = (const float4*)(s_x + bb * SX_STRIDE);
    const float4* sxb = (const float4*)(s_x + (bb + 16) * SX_STRIDE);

#pragma unroll 2
    for (int il = 0; il < ni; il++) {
        const int cur = il & 1;
        const bool wok = (il + 1 < ni);

        // prefetch W(il+1), (pass2) prior logit
        float4 wpf;
        if (wok) wpf = *(const float4*)(wsrc);
        float gb1 = 0.f, gb2 = 0.f;
        if (PASS == 2) {
            float go = *gbp;
            float gt = __shfl_xor_sync(0xffffffffu, go, 16);
            gb1 = dh ? gt : go;
            gb2 = dh ? go : gt;
        }

        // ---- consume stage il-1 (t2 holds t(il-1); e(il-1) in s_e[1-cur])
        if (il > 0) {
            if (PASS > 0) {
                const float* se = s_e + (1 - cur) * 352 + l * 11;
                float Z = ((se[0] + se[1]) + (se[2] + se[3])) +
                          ((se[4] + se[5]) + (se[6] + se[7])) + (se[8] + se[9]);
                float Zo = __shfl_xor_sync(0xffffffffu, Z, 16);
                float Z1 = dh ? Zo : Z;
                float Z2 = dh ? Z : Zo;
                float c1 = __fdividef(e1p, Z1);
                float c2 = __fdividef(e2p, Z2);
                ull cp1 = pack2(c1, c1), cp2 = pack2(c2, c2);
#pragma unroll
                for (int j = 0; j < 4; j++) {
                    sa[j] = ffma2(cp1, t2a[j], sa[j]);
                    sb[j] = ffma2(cp2, t2b[j], sb[j]);
                }
            } else {
#pragma unroll
                for (int j = 0; j < 4; j++) {
                    sa[j] = fadd2(sa[j], t2a[j]);
                    sb[j] = fadd2(sb[j], t2b[j]);
                }
            }
        }

        // ---- x(il): 2 x LDS.128 per batch
        float xa[8], xb[8];
        {
            const float4* xra = sxa + il * 2;
            const float4* xrb = sxb + il * 2;
            float4 a0 = xra[0], a1 = xra[1], c0 = xrb[0], c1 = xrb[1];
            xa[0] = a0.x; xa[1] = a0.y; xa[2] = a0.z; xa[3] = a0.w;
            xa[4] = a1.x; xa[5] = a1.y; xa[6] = a1.z; xa[7] = a1.w;
            xb[0] = c0.x; xb[1] = c0.y; xb[2] = c0.z; xb[3] = c0.w;
            xb[4] = c1.x; xb[5] = c1.y; xb[6] = c1.z; xb[7] = c1.w;
        }

        // ---- t(il) = u[b, i, n, d-half] for both batches
#pragma unroll
        for (int j = 0; j < 4; j++) { t2a[j] = 0ULL; t2b[j] = 0ULL; }
        {
            const float* wb = s_w + cur * 1280 + n * 128 + dh * 8;
#pragma unroll
            for (int p = 0; p < P_; p++) {
                ull xpa = pack2(xa[p], xa[p]);
                ull xpb = pack2(xb[p], xb[p]);
                ulonglong2 w0 = *(const ulonglong2*)(wb + p * 16);
                ulonglong2 w1 = *(const ulonglong2*)(wb + p * 16 + 4);
                t2a[0] = ffma2(xpa, w0.x, t2a[0]); t2a[1] = ffma2(xpa, w0.y, t2a[1]);
                t2a[2] = ffma2(xpa, w1.x, t2a[2]); t2a[3] = ffma2(xpa, w1.y, t2a[3]);
                t2b[0] = ffma2(xpb, w0.x, t2b[0]); t2b[1] = ffma2(xpb, w0.y, t2b[1]);
                t2b[2] = ffma2(xpb, w1.x, t2b[2]); t2b[3] = ffma2(xpb, w1.y, t2b[3]);
            }
        }

        // ---- agreement + exp (log2 domain)
        if (PASS > 0) {
            ull aa = 0ULL, ab = 0ULL;
#pragma unroll
            for (int j = 0; j < 4; j++) {
                aa = ffma2(t2a[j], v2a[j], aa);
                ab = ffma2(t2b[j], v2b[j], ab);
            }
            float2 fa = unpack2(aa); float pa = fa.x + fa.y;
            float2 fb = unpack2(ab); float pb = fb.x + fb.y;
            float pao = __shfl_xor_sync(0xffffffffu, pa, 16);
            float pbo = __shfl_xor_sync(0xffffffffu, pb, 16);
            float bn1 = pa + pao + gb1;
            float bn2 = pb + pbo + gb2;
            if (PASS == 1) *gbp = dh ? bn2 : bn1;   // PASS2 is last: no store
            e1p = fast_ex2(bn1);
            e2p = fast_ex2(bn2);
            s_e[cur * 352 + l * 11 + n] = dh ? e2p : e1p;
        }
        if (PASS > 0) gbp += 640;
        if (wok) {
            *(float4*)(s_w + (1 - cur) * 1280 + tid * 4) = wpf;
            wsrc += 1280;
        }

        __syncthreads();
    }

    // ---- epilogue: consume last stage
    {
        const int prev = (ni - 1) & 1;
        if (PASS > 0) {
            const float* se = s_e + prev * 352 + l * 11;
            float Z = ((se[0] + se[1]) + (se[2] + se[3])) +
                      ((se[4] + se[5]) + (se[6] + se[7])) + (se[8] + se[9]);
            float Zo = __shfl_xor_sync(0xffffffffu, Z, 16);
            float Z1 = dh ? Zo : Z;
            float Z2 = dh ? Z : Zo;
            float c1 = __fdividef(e1p, Z1);
            float c2 = __fdividef(e2p, Z2);
            ull cp1 = pack2(c1, c1), cp2 = pack2(c2, c2);
#pragma unroll
            for (int j = 0; j < 4; j++) {
                sa[j] = ffma2(cp1, t2a[j], sa[j]);
                sb[j] = ffma2(cp2, t2b[j], sb[j]);
            }
        } else {
#pragma unroll
            for (int j = 0; j < 4; j++) {
                sa[j] = fadd2(sa[j], t2a[j]);
                sb[j] = fadd2(sb[j], t2b[j]);
            }
        }
    }

    // ---- vector-atomic accumulation (REDG.128, spread addresses)
    {
        float2 a0 = unpack2(sa[0]), a1 = unpack2(sa[1]);
        float2 a2 = unpack2(sa[2]), a3 = unpack2(sa[3]);
        float2 c0 = unpack2(sb[0]), c1 = unpack2(sb[1]);
        float2 c2 = unpack2(sb[2]), c3 = unpack2(sb[3]);
        float k = (PASS == 0) ? 0.1f : 1.0f;
        float4* s1 = (float4*)(g_s + b1 * ND_ + n * D_ + dh * 8);
        float4* s2 = (float4*)(g_s + b2 * ND_ + n * D_ + dh * 8);
        atomicAdd(s1,     make_float4(a0.x * k, a0.y * k, a1.x * k, a1.y * k));
        atomicAdd(s1 + 1, make_float4(a2.x * k, a2.y * k, a3.x * k, a3.y * k));
        atomicAdd(s2,     make_float4(c0.x * k, c0.y * k, c1.x * k, c1.y * k));
        atomicAdd(s2 + 1, make_float4(c2.x * k, c2.y * k, c3.x * k, c3.y * k));
    }
}

// Elementwise squash; re-zeroes g_s for the next pass. Grid 40 x 256.
template <bool FINAL>
__global__ __launch_bounds__(256) void k_squash(float* __restrict__ dout) {
    int idx = blockIdx.x * 256 + threadIdx.x;
    if (idx < OUT_) {
        float s = g_s[idx];
        g_s[idx] = 0.0f;
        float sq = s * s;
        float scale = sq / ((1.f + sq) * sqrtf(sq + 1e-7f));
        float v = scale * s;
        if (FINAL) dout[idx] = v;
        else       g_v[idx] = v;
    }
}

extern "C" void kernel_launch(void* const* d_in, const int* in_sizes, int n_in,
                              void* d_out, int out_size) {
    const float* X = (const float*)d_in[0];
    const float* W = (const float*)d_in[1];
    if (n_in >= 2 && in_sizes[0] != B_ * I_ * P_) {
        const float* tmp = X; X = W; W = tmp;
    }

    dim3 gp(148, 2);
    k_pad<<<40, 256>>>();                               // zero g_s; ncu -s 5 -> k_pass<2>
    k_pass<0><<<gp, THREADS, SMEM_BYTES>>>(X, W);
    k_squash<false><<<40, 256>>>(nullptr);
    k_pass<1><<<gp, THREADS, SMEM_BYTES>>>(X, W);
    k_squash<false><<<40, 256>>>(nullptr);
    k_pass<2><<<gp, THREADS, SMEM_BYTES>>>(X, W);
    k_squash<true><<<40, 256>>>((float*)d_out);
}

// round 13
// speedup vs baseline: 2.2095x; 1.0561x over previous
#include <cuda_runtime.h>

// DigitCaps dynamic routing, GB300 sm_103a — R13.
// B=64, I=4096, Din=8, N=10, D=16, 3 routing iterations.
//
// R13 = R6 k_pass (best fabric, 39.2us/pass) + fixed reduction path:
//  - 16-replica atomic accumulation g_srep[pass][16][10240], replica = cb&15:
//    depth per address 148 -> ~19 (R12's single-copy atomics serialized
//    ~148-deep at end-of-kernel burst -> +1.2us/pass tail; falsified)
//  - per-pass replica sets (no inter-pass zeroing); k_pad zeroes all once
//  - k_squash: depth-16 fixed-order sum + elementwise squash (~2us vs 6us
//    latency-bound k_finish)

#define B_ 64
#define I_ 4096
#define P_ 8
#define N_ 10
#define D_ 16
#define ND_ 160
#define THREADS 320              // 32 b x 10 n, lane = 16bb x 2dh, BTILE=2
#define OUT_ (B_ * ND_)          // 10240
#define NREP 16
#define L2E 1.4426950408889634f

#define SX_STRIDE 236
#define SX_SZ (32 * SX_STRIDE)   // 7552 floats
#define SW_SZ (2 * 1280)
#define SE_SZ (2 * 352)
#define SMEM_BYTES ((SX_SZ + SW_SZ + SE_SZ) * 4)   // 43,264 B (< 48K default)

__device__ float g_srep[3][NREP][OUT_];         // replicated atomic accumulators, 2MB
__device__ float g_blog[(size_t)I_ * 640];      // log2-domain logits [i][n*64+bh*32+l]
__device__ float g_v[OUT_];                     // squashed v

typedef unsigned long long ull;

static __device__ __forceinline__ ull pack2(float a, float b) {
    ull r; asm("mov.b64 %0, {%1,%2};" : "=l"(r) : "f"(a), "f"(b)); return r;
}
static __device__ __forceinline__ float2 unpack2(ull v) {
    float2 r; asm("mov.b64 {%0,%1}, %2;" : "=f"(r.x), "=f"(r.y) : "l"(v)); return r;
}
static __device__ __forceinline__ ull ffma2(ull a, ull b, ull c) {
    ull d; asm("fma.rn.f32x2 %0, %1, %2, %3;" : "=l"(d) : "l"(a), "l"(b), "l"(c)); return d;
}
static __device__ __forceinline__ ull fadd2(ull a, ull b) {
    ull d; asm("add.rn.f32x2 %0, %1, %2;" : "=l"(d) : "l"(a), "l"(b)); return d;
}
static __device__ __forceinline__ float fast_ex2(float x) {
    float r; asm("ex2.approx.f32 %0, %1;" : "=f"(r) : "f"(x)); return r;
}

// launch #0: zero all replica sets (491,520 floats; ~2MB of STG)
__global__ __launch_bounds__(256) void k_pad() {
    int idx = blockIdx.x * 256 + threadIdx.x;
    if (idx < 3 * NREP * OUT_) ((float*)g_srep)[idx] = 0.0f;
}

template <int PASS>
__global__ __launch_bounds__(THREADS, 2) void k_pass(const float* __restrict__ X,
                                                     const float* __restrict__ W) {
    extern __shared__ float smem[];
    float* s_x = smem;                 // [lb][r] stride SX_STRIDE
    float* s_w = smem + SX_SZ;         // 2 x 1280
    float* s_e = s_w + SW_SZ;          // 2 x (32*11)

    const int tid = threadIdx.x;
    const int n   = tid >> 5;          // warp id = n
    const int l   = tid & 31;          // lane
    const int bb  = l & 15;
    const int dh  = l >> 4;            // d-half
    const int cb  = blockIdx.x;        // i-chunk
    const int bh  = blockIdx.y;        // batch half
    int i0, ni;
    if (cb < 100) { i0 = cb * 28; ni = 28; }
    else          { i0 = 2800 + (cb - 100) * 27; ni = 27; }
    const int b1 = bh * 32 + bb;
    const int b2 = b1 + 16;

    // ---- stage x: rows = 32 local batches, ni*8 floats each
    {
        int nr = ni * 8;
        for (int idx = tid; idx < 32 * nr; idx += THREADS) {
            int lb = idx / nr;
            int r  = idx - lb * nr;
            s_x[lb * SX_STRIDE + r] = X[(size_t)(bh * 32 + lb) * (I_ * P_) + i0 * P_ + r];
        }
    }
    // ---- stage W(0)
    *(float4*)(s_w + tid * 4) = *(const float4*)(W + (size_t)i0 * 1280 + tid * 4);

    // ---- v (log2-scaled) for both batches, this thread's d-half
    ull v2a[4], v2b[4];
    if (PASS > 0) {
        const float4* va = (const float4*)(g_v + b1 * ND_ + n * D_ + dh * 8);
        const float4* vb = (const float4*)(g_v + b2 * ND_ + n * D_ + dh * 8);
        float4 a0 = va[0], a1 = va[1], c0 = vb[0], c1 = vb[1];
        v2a[0] = pack2(a0.x * L2E, a0.y * L2E); v2a[1] = pack2(a0.z * L2E, a0.w * L2E);
        v2a[2] = pack2(a1.x * L2E, a1.y * L2E); v2a[3] = pack2(a1.z * L2E, a1.w * L2E);
        v2b[0] = pack2(c0.x * L2E, c0.y * L2E); v2b[1] = pack2(c0.z * L2E, c0.w * L2E);
        v2b[2] = pack2(c1.x * L2E, c1.y * L2E); v2b[3] = pack2(c1.z * L2E, c1.w * L2E);
    }
    __syncthreads();

    ull t2a[4], t2b[4], sa[4], sb[4];
#pragma unroll
    for (int j = 0; j < 4; j++) { sa[j] = 0ULL; sb[j] = 0ULL; }
    float e1p = 0.f, e2p = 0.f;

    const float* wsrc = W + (size_t)(i0 + 1) * 1280 + tid * 4;
    float* gbp = g_blog + (size_t)i0 * 640 + n * 64 + bh * 32 + l;
    const float4* sxa = (const float4*)(s_x + bb * SX_STRIDE);
    const float4* sxb = (const float4*)(s_x + (bb + 16) * SX_STRIDE);

#pragma unroll 2
    for (int il = 0; il < ni; il++) {
        const int cur = il & 1;
        const bool wok = (il + 1 < ni);

        // prefetch W(il+1), (pass2) prior logit
        float4 wpf;
        if (wok) wpf = *(const float4*)(wsrc);
        float gb1 = 0.f, gb2 = 0.f;
        if (PASS == 2) {
            float go = *gbp;
            float gt = __shfl_xor_sync(0xffffffffu, go, 16);
            gb1 = dh ? gt : go;
            gb2 = dh ? go : gt;
        }

        // ---- consume stage il-1 (t2 holds t(il-1); e(il-1) in s_e[1-cur])
        if (il > 0) {
            if (PASS > 0) {
                const float* se = s_e + (1 - cur) * 352 + l * 11;
                float Z = ((se[0] + se[1]) + (se[2] + se[3])) +
                          ((se[4] + se[5]) + (se[6] + se[7])) + (se[8] + se[9]);
                float Zo = __shfl_xor_sync(0xffffffffu, Z, 16);
                float Z1 = dh ? Zo : Z;
                float Z2 = dh ? Z : Zo;
                float c1 = __fdividef(e1p, Z1);
                float c2 = __fdividef(e2p, Z2);
                ull cp1 = pack2(c1, c1), cp2 = pack2(c2, c2);
#pragma unroll
                for (int j = 0; j < 4; j++) {
                    sa[j] = ffma2(cp1, t2a[j], sa[j]);
                    sb[j] = ffma2(cp2, t2b[j], sb[j]);
                }
            } else {
#pragma unroll
                for (int j = 0; j < 4; j++) {
                    sa[j] = fadd2(sa[j], t2a[j]);
                    sb[j] = fadd2(sb[j], t2b[j]);
                }
            }
        }

        // ---- x(il): 2 x LDS.128 per batch
        float xa[8], xb[8];
        {
            const float4* xra = sxa + il * 2;
            const float4* xrb = sxb + il * 2;
            float4 a0 = xra[0], a1 = xra[1], c0 = xrb[0], c1 = xrb[1];
            xa[0] = a0.x; xa[1] = a0.y; xa[2] = a0.z; xa[3] = a0.w;
            xa[4] = a1.x; xa[5] = a1.y; xa[6] = a1.z; xa[7] = a1.w;
            xb[0] = c0.x; xb[1] = c0.y; xb[2] = c0.z; xb[3] = c0.w;
            xb[4] = c1.x; xb[5] = c1.y; xb[6] = c1.z; xb[7] = c1.w;
        }

        // ---- t(il) = u[b, i, n, d-half] for both batches
#pragma unroll
        for (int j = 0; j < 4; j++) { t2a[j] = 0ULL; t2b[j] = 0ULL; }
        {
            const float* wb = s_w + cur * 1280 + n * 128 + dh * 8;
#pragma unroll
            for (int p = 0; p < P_; p++) {
                ull xpa = pack2(xa[p], xa[p]);
                ull xpb = pack2(xb[p], xb[p]);
                ulonglong2 w0 = *(const ulonglong2*)(wb + p * 16);
                ulonglong2 w1 = *(const ulonglong2*)(wb + p * 16 + 4);
                t2a[0] = ffma2(xpa, w0.x, t2a[0]); t2a[1] = ffma2(xpa, w0.y, t2a[1]);
                t2a[2] = ffma2(xpa, w1.x, t2a[2]); t2a[3] = ffma2(xpa, w1.y, t2a[3]);
                t2b[0] = ffma2(xpb, w0.x, t2b[0]); t2b[1] = ffma2(xpb, w0.y, t2b[1]);
                t2b[2] = ffma2(xpb, w1.x, t2b[2]); t2b[3] = ffma2(xpb, w1.y, t2b[3]);
            }
        }

        // ---- agreement + exp (log2 domain)
        if (PASS > 0) {
            ull aa = 0ULL, ab = 0ULL;
#pragma unroll
            for (int j = 0; j < 4; j++) {
                aa = ffma2(t2a[j], v2a[j], aa);
                ab = ffma2(t2b[j], v2b[j], ab);
            }
            float2 fa = unpack2(aa); float pa = fa.x + fa.y;
            float2 fb = unpack2(ab); float pb = fb.x + fb.y;
            float pao = __shfl_xor_sync(0xffffffffu, pa, 16);
            float pbo = __shfl_xor_sync(0xffffffffu, pb, 16);
            float bn1 = pa + pao + gb1;
            float bn2 = pb + pbo + gb2;
            if (PASS == 1) *gbp = dh ? bn2 : bn1;   // PASS2 is last: no store
            e1p = fast_ex2(bn1);
            e2p = fast_ex2(bn2);
            s_e[cur * 352 + l * 11 + n] = dh ? e2p : e1p;
        }
        if (PASS > 0) gbp += 640;
        if (wok) {
            *(float4*)(s_w + (1 - cur) * 1280 + tid * 4) = wpf;
            wsrc += 1280;
        }

        __syncthreads();
    }

    // ---- epilogue: consume last stage
    {
        const int prev = (ni - 1) & 1;
        if (PASS > 0) {
            const float* se = s_e + prev * 352 + l * 11;
            float Z = ((se[0] + se[1]) + (se[2] + se[3])) +
                      ((se[4] + se[5]) + (se[6] + se[7])) + (se[8] + se[9]);
            float Zo = __shfl_xor_sync(0xffffffffu, Z, 16);
            float Z1 = dh ? Zo : Z;
            float Z2 = dh ? Z : Zo;
            float c1 = __fdividef(e1p, Z1);
            float c2 = __fdividef(e2p, Z2);
            ull cp1 = pack2(c1, c1), cp2 = pack2(c2, c2);
#pragma unroll
            for (int j = 0; j < 4; j++) {
                sa[j] = ffma2(cp1, t2a[j], sa[j]);
                sb[j] = ffma2(cp2, t2b[j], sb[j]);
            }
        } else {
#pragma unroll
            for (int j = 0; j < 4; j++) {
                sa[j] = fadd2(sa[j], t2a[j]);
                sb[j] = fadd2(sb[j], t2b[j]);
            }
        }
    }

    // ---- replicated vector-atomic accumulation (depth ~19 per address)
    {
        float2 a0 = unpack2(sa[0]), a1 = unpack2(sa[1]);
        float2 a2 = unpack2(sa[2]), a3 = unpack2(sa[3]);
        float2 c0 = unpack2(sb[0]), c1 = unpack2(sb[1]);
        float2 c2 = unpack2(sb[2]), c3 = unpack2(sb[3]);
        float k = (PASS == 0) ? 0.1f : 1.0f;
        float* base = &g_srep[PASS][cb & (NREP - 1)][0];
        float4* s1 = (float4*)(base + b1 * ND_ + n * D_ + dh * 8);
        float4* s2 = (float4*)(base + b2 * ND_ + n * D_ + dh * 8);
        atomicAdd(s1,     make_float4(a0.x * k, a0.y * k, a1.x * k, a1.y * k));
        atomicAdd(s1 + 1, make_float4(a2.x * k, a2.y * k, a3.x * k, a3.y * k));
        atomicAdd(s2,     make_float4(c0.x * k, c0.y * k, c1.x * k, c1.y * k));
        atomicAdd(s2 + 1, make_float4(c2.x * k, c2.y * k, c3.x * k, c3.y * k));
    }
}

// Depth-16 fixed-order replica sum + elementwise squash. Grid 40 x 256.
template <int PSET, bool FINAL>
__global__ __launch_bounds__(256) void k_squash(float* __restrict__ dout) {
    int idx = blockIdx.x * 256 + threadIdx.x;
    if (idx < OUT_) {
        const float* p = &g_srep[PSET][0][0] + idx;
        float a0 = 0.f, a1 = 0.f, a2 = 0.f, a3 = 0.f;
#pragma unroll
        for (int r = 0; r < NREP; r += 4) {
            a0 += p[(r + 0) * OUT_];
            a1 += p[(r + 1) * OUT_];
            a2 += p[(r + 2) * OUT_];
            a3 += p[(r + 3) * OUT_];
        }
        float s = (a0 + a1) + (a2 + a3);
        float sq = s * s;
        float scale = sq / ((1.f + sq) * sqrtf(sq + 1e-7f));
        float v = scale * s;
        if (FINAL) dout[idx] = v;
        else       g_v[idx] = v;
    }
}

extern "C" void kernel_launch(void* const* d_in, const int* in_sizes, int n_in,
                              void* d_out, int out_size) {
    const float* X = (const float*)d_in[0];
    const float* W = (const float*)d_in[1];
    if (n_in >= 2 && in_sizes[0] != B_ * I_ * P_) {
        const float* tmp = X; X = W; W = tmp;
    }

    dim3 gp(148, 2);
    k_pad<<<1920, 256>>>();                              // zero replicas; ncu -s 5 -> k_pass<2>
    k_pass<0><<<gp, THREADS, SMEM_BYTES>>>(X, W);
    k_squash<0, false><<<40, 256>>>(nullptr);
    k_pass<1><<<gp, THREADS, SMEM_BYTES>>>(X, W);
    k_squash<1, false><<<40, 256>>>(nullptr);
    k_pass<2><<<gp, THREADS, SMEM_BYTES>>>(X, W);
    k_squash<2, true><<<40, 256>>>((float*)d_out);
}